// round 5
// baseline (speedup 1.0000x reference)
#include <cuda_runtime.h>
#include <cuda_bf16.h>
#include <math.h>
#include <stdint.h>

// Problem constants
#define BATCH   2
#define NPTS    2048
#define HEADS   8
#define DHEAD   64
#define KNB     32
#define DIMF    512
#define INNER   512          // HEADS*DHEAD
#define QKVN    1536         // 3*INNER
#define ROWS    (BATCH*NPTS) // 4096
#define FEAT_OUT (ROWS*DIMF) // 2097152

#define U64MAX 0xFFFFFFFFFFFFFFFFULL

// Scratch (device globals: allocation-free per harness rules)
__device__ float g_qkv[ROWS * QKVN];   // 25.2 MB
__device__ float g_att[ROWS * INNER];  // 8.4 MB

// ---------------------------------------------------------------------------
// TF32 tensor-core GEMM, 2-stage smem ping-pong (one barrier per K-tile).
// C[M,N] = A[M,K] @ B[K,N] (+ bias[N]); block 128x128x32, 8 warps (2x4),
// warp tile 64x32 via mma.sync.m16n8k8.
// ---------------------------------------------------------------------------
__device__ __forceinline__ uint32_t f2tf32(float x) {
    uint32_t r;
    asm("cvt.rna.tf32.f32 %0, %1;" : "=r"(r) : "f"(x));
    return r;
}

#define GBM 128
#define GBN 128
#define GBK 32
#define GAP 36
#define GBP 136
#define GSTAGE (GBM*GAP + GBK*GBP)   // words per stage: 8960
#define GSMEM_BYTES (2 * GSTAGE * 4) // 71680 bytes

__global__ __launch_bounds__(256, 2) void tf32_gemm_kernel(
    const float* __restrict__ A, const float* __restrict__ Bm,
    float* __restrict__ C, int M, int N, int K,
    const float* __restrict__ bias)
{
    extern __shared__ uint32_t smem[];

    const int tid = threadIdx.x;
    const int lane = tid & 31;
    const int wid = tid >> 5;
    const int wm = wid & 1;
    const int wn = wid >> 1;
    const int row0 = blockIdx.y * GBM;
    const int col0 = blockIdx.x * GBN;

    const int g  = lane >> 2;
    const int tg = lane & 3;

    float acc[4][4][4];
#pragma unroll
    for (int i = 0; i < 4; i++)
#pragma unroll
        for (int j = 0; j < 4; j++)
#pragma unroll
            for (int r = 0; r < 4; r++) acc[i][j][r] = 0.f;

    const int ar = tid >> 3;           // 0..31 (+p*32)
    const int ac = (tid & 7) * 4;      // 0..28
    const int br = tid >> 5;           // 0..7  (+p*8)
    const int bc = (tid & 31) * 4;     // 0..124

    float4 pa[4], pb[4];
#pragma unroll
    for (int p = 0; p < 4; p++) {
        pa[p] = *(const float4*)&A[(long)(row0 + ar + p * 32) * K + ac];
        pb[p] = *(const float4*)&Bm[(long)(br + p * 8) * N + col0 + bc];
    }
    // STS stage 0
#pragma unroll
    for (int p = 0; p < 4; p++) {
        uint32_t* as = &smem[(ar + p * 32) * GAP + ac];
        as[0] = f2tf32(pa[p].x); as[1] = f2tf32(pa[p].y);
        as[2] = f2tf32(pa[p].z); as[3] = f2tf32(pa[p].w);
        uint32_t* bs = &smem[GBM * GAP + (br + p * 8) * GBP + bc];
        bs[0] = f2tf32(pb[p].x); bs[1] = f2tf32(pb[p].y);
        bs[2] = f2tf32(pb[p].z); bs[3] = f2tf32(pb[p].w);
    }
    __syncthreads();

    int stage = 0;
    for (int kk = 0; kk < K; kk += GBK) {
        const bool has_next = (kk + GBK) < K;
        if (has_next) {
#pragma unroll
            for (int p = 0; p < 4; p++) {
                pa[p] = *(const float4*)&A[(long)(row0 + ar + p * 32) * K + kk + GBK + ac];
                pb[p] = *(const float4*)&Bm[(long)(kk + GBK + br + p * 8) * N + col0 + bc];
            }
        }

        const uint32_t* As = &smem[stage * GSTAGE];
        const uint32_t* Bs = &smem[stage * GSTAGE + GBM * GAP];
#pragma unroll
        for (int ks = 0; ks < 4; ks++) {
            const int k0 = ks * 8;
            uint32_t a[4][4], b[4][2];
#pragma unroll
            for (int mi = 0; mi < 4; mi++) {
                const int r = wm * 64 + mi * 16 + g;
                a[mi][0] = As[r * GAP + k0 + tg];
                a[mi][1] = As[(r + 8) * GAP + k0 + tg];
                a[mi][2] = As[r * GAP + k0 + tg + 4];
                a[mi][3] = As[(r + 8) * GAP + k0 + tg + 4];
            }
#pragma unroll
            for (int nj = 0; nj < 4; nj++) {
                const int c = wn * 32 + nj * 8 + g;
                b[nj][0] = Bs[(k0 + tg) * GBP + c];
                b[nj][1] = Bs[(k0 + tg + 4) * GBP + c];
            }
#pragma unroll
            for (int mi = 0; mi < 4; mi++)
#pragma unroll
                for (int nj = 0; nj < 4; nj++) {
                    asm volatile(
                        "mma.sync.aligned.m16n8k8.row.col.f32.tf32.tf32.f32 "
                        "{%0,%1,%2,%3}, {%4,%5,%6,%7}, {%8,%9}, {%0,%1,%2,%3};"
                        : "+f"(acc[mi][nj][0]), "+f"(acc[mi][nj][1]),
                          "+f"(acc[mi][nj][2]), "+f"(acc[mi][nj][3])
                        : "r"(a[mi][0]), "r"(a[mi][1]), "r"(a[mi][2]), "r"(a[mi][3]),
                          "r"(b[nj][0]), "r"(b[nj][1]));
                }
        }

        if (has_next) {
            const int ns = stage ^ 1;
#pragma unroll
            for (int p = 0; p < 4; p++) {
                uint32_t* as = &smem[ns * GSTAGE + (ar + p * 32) * GAP + ac];
                as[0] = f2tf32(pa[p].x); as[1] = f2tf32(pa[p].y);
                as[2] = f2tf32(pa[p].z); as[3] = f2tf32(pa[p].w);
                uint32_t* bs = &smem[ns * GSTAGE + GBM * GAP + (br + p * 8) * GBP + bc];
                bs[0] = f2tf32(pb[p].x); bs[1] = f2tf32(pb[p].y);
                bs[2] = f2tf32(pb[p].z); bs[3] = f2tf32(pb[p].w);
            }
            __syncthreads();
            stage = ns;
        }
    }

#pragma unroll
    for (int mi = 0; mi < 4; mi++) {
        const int r = row0 + wm * 64 + mi * 16 + g;
#pragma unroll
        for (int nj = 0; nj < 4; nj++) {
            const int c = col0 + wn * 32 + nj * 8 + 2 * tg;
            float b0 = bias ? bias[c] : 0.f;
            float b1 = bias ? bias[c + 1] : 0.f;
            C[(long)r * N + c]           = acc[mi][nj][0] + b0;
            C[(long)r * N + c + 1]       = acc[mi][nj][1] + b1;
            C[(long)(r + 8) * N + c]     = acc[mi][nj][2] + b0;
            C[(long)(r + 8) * N + c + 1] = acc[mi][nj][3] + b1;
        }
    }
}

// ---------------------------------------------------------------------------
// Warp-level top-2-per-round extraction over per-lane key arrays.
// keys: NK u64 per lane, modified in place (winners -> U64MAX).
// Returns (m1, m2) = two smallest keys warp-wide (all lanes).
// ---------------------------------------------------------------------------
template<int NK>
__device__ __forceinline__ void warp_top2(unsigned long long (&keys)[NK],
                                          unsigned long long& om1,
                                          unsigned long long& om2)
{
    unsigned long long m1 = U64MAX, m2 = U64MAX;
#pragma unroll
    for (int u = 0; u < NK; u++) {
        unsigned long long k = keys[u];
        if (k < m1) { m2 = m1; m1 = k; }
        else if (k < m2) { m2 = k; }
    }
#pragma unroll
    for (int off = 16; off; off >>= 1) {
        unsigned long long o1 = __shfl_xor_sync(0xFFFFFFFFu, m1, off);
        unsigned long long o2 = __shfl_xor_sync(0xFFFFFFFFu, m2, off);
        unsigned long long lo = min(m1, o1);
        unsigned long long hi = max(m1, o1);
        m2 = min(hi, min(m2, o2));
        m1 = lo;
    }
#pragma unroll
    for (int u = 0; u < NK; u++)
        if (keys[u] == m1 || keys[u] == m2) keys[u] = U64MAX;
    om1 = m1; om2 = m2;
}

// ---------------------------------------------------------------------------
// Fused selection + attention kernel. One block (256 threads) per query row.
// ---------------------------------------------------------------------------
__global__ __launch_bounds__(256) void sa_kernel(
    const float* __restrict__ coors,
    const float* __restrict__ wc1, const float* __restrict__ bc1,
    const float* __restrict__ wc2, const float* __restrict__ bc2,
    const float* __restrict__ wg,  const float* __restrict__ bg,
    const float* __restrict__ coors_scale,
    const float* __restrict__ coors_combine,
    float* __restrict__ out_coors)
{
    const int row = blockIdx.x;
    const int b = row >> 11;             // / NPTS
    const int i = row & (NPTS - 1);
    const int tid = threadIdx.x;
    const int lane = tid & 31;
    const int warp = tid >> 5;           // warp == head

    __shared__ unsigned long long s_cand[256];
    __shared__ int   s_idx[KNB];
    __shared__ float s_dist[KNB];
    __shared__ float s_cos[KNB][32];
    __shared__ float s_sin[KNB][32];
    __shared__ float s_qk[HEADS][KNB];
    __shared__ float s_attn[HEADS][KNB];
    __shared__ float s_cw[KNB][HEADS];
    __shared__ float s_gate[KNB][HEADS];
    __shared__ float s_hid[KNB][16];
    __shared__ float s_ci[3];

    const float* cb = coors + (long)b * NPTS * 3;
    if (tid < 3) s_ci[tid] = cb[i * 3 + tid];
    __syncthreads();
    const float cix = s_ci[0], ciy = s_ci[1], ciz = s_ci[2];

    // q preloads (rotary with zero freqs is identity)
    const int hb = warp * DHEAD;
    const long qbase = (long)row * QKVN + hb;
    const float2 qp = *(const float2*)&g_qkv[qbase + 2 * lane];  // q[2l], q[2l+1]
    const float qA = g_qkv[qbase + lane];                        // q[l]
    const float qB = g_qkv[qbase + lane + 32];                   // q[l+32]

    // squared distances: warp w owns points [w*256, w*256+256)
    unsigned long long keys[8];
#pragma unroll
    for (int u = 0; u < 8; u++) {
        int j = warp * 256 + u * 32 + lane;
        float dx = cix - cb[j * 3 + 0];
        float dy = ciy - cb[j * 3 + 1];
        float dz = ciz - cb[j * 3 + 2];
        float d2 = dx * dx + dy * dy + dz * dz;
        keys[u] = ((unsigned long long)__float_as_uint(d2) << 32) | (unsigned)j;
    }

    // Phase A: per-warp top-32, two per round (no barriers, no atomics)
#pragma unroll 1
    for (int r = 0; r < 16; r++) {
        unsigned long long m1, m2;
        warp_top2<8>(keys, m1, m2);
        if (lane == 0) {
            s_cand[warp * 32 + 2 * r]     = m1;
            s_cand[warp * 32 + 2 * r + 1] = m2;
        }
    }
    __syncthreads();

    // Phase B: warp 0 merges 256 candidates -> global top-32
    if (warp == 0) {
        unsigned long long ck[8];
#pragma unroll
        for (int u = 0; u < 8; u++) ck[u] = s_cand[u * 32 + lane];
#pragma unroll 1
        for (int r = 0; r < 16; r++) {
            unsigned long long m1, m2;
            warp_top2<8>(ck, m1, m2);
            if (lane == 0) {
                s_idx[2 * r]      = (int)(m1 & 0xFFFFFFFFu);
                s_dist[2 * r]     = sqrtf(__uint_as_float((unsigned)(m1 >> 32)));
                s_idx[2 * r + 1]  = (int)(m2 & 0xFFFFFFFFu);
                s_dist[2 * r + 1] = sqrtf(__uint_as_float((unsigned)(m2 >> 32)));
            }
        }
    }
    __syncthreads();

    // rotary cos/sin: freqs[m] = min(dist*100,5000) * 10000^(-2m/64)
    for (int idx = tid; idx < KNB * 32; idx += 256) {
        int r = idx >> 5, m = idx & 31;
        float t = fminf(s_dist[r] * 100.0f, 5000.0f);
        float invf = exp2f((float)m * -0.41524099657040455f);
        float f = t * invf;
        float s, c;
        sincosf(f, &s, &c);
        s_cos[r][m] = c;
        s_sin[r][m] = s;
    }
    __syncthreads();

    // qk logits: lane l holds k pair (2l, 2l+1); zero rotate-half shuffles.
    // qk = sum_l C[l]*(q[2l]k[2l]+q[2l+1]k[2l+1]) + S[16+l/2]*q[l+32]*k[2l]
    //           - S[l/2]*q[l]*k[2l+1]
    const int si1 = lane >> 1;
    const int si2 = 16 + (lane >> 1);
#pragma unroll 4
    for (int r = 0; r < KNB; r++) {
        const long kb = (long)(b * NPTS + s_idx[r]) * QKVN + INNER + hb;
        float2 kv = *(const float2*)&g_qkv[kb + 2 * lane];
        float C  = s_cos[r][lane];
        float S1 = s_sin[r][si1];
        float S2 = s_sin[r][si2];
        float t = fmaf(qp.y, kv.y, qp.x * kv.x);
        float sum = C * t;
        sum = fmaf(S2, qB * kv.x, sum);
        sum = fmaf(-S1, qA * kv.y, sum);
#pragma unroll
        for (int off = 16; off; off >>= 1)
            sum += __shfl_down_sync(0xFFFFFFFFu, sum, off);
        if (lane == 0) s_qk[warp][r] = sum * 0.125f;
    }
    __syncthreads();

    // tiny MLPs, parallel over (neighbor j, head/slot s): tid = j*8 + s
    {
        const int j = tid >> 3;
        const int s = tid & 7;
        float in[HEADS];
#pragma unroll
        for (int h = 0; h < HEADS; h++) in[h] = s_qk[h][j];
#pragma unroll
        for (int t = 0; t < 2; t++) {
            const int m = 2 * s + t;
            float a = bc1[m];
#pragma unroll
            for (int h = 0; h < HEADS; h++) a += in[h] * wc1[h * 16 + m];
            float x3 = a * a * a;
            float tt = tanhf(0.7978845608028654f * (a + 0.044715f * x3));
            s_hid[j][m] = 0.5f * a * (1.0f + tt);
        }
        __syncwarp();
        float a = bc2[s];
#pragma unroll
        for (int m = 0; m < 16; m++) a += s_hid[j][m] * wc2[m * 8 + s];
        s_cw[j][s] = a;
        float gg = bg[s];
#pragma unroll
        for (int h = 0; h < HEADS; h++) gg += in[h] * wg[h * 8 + s];
        s_gate[j][s] = tanhf(gg);
    }
    __syncthreads();

    // softmaxes: warp h handles head h, lane j handles neighbor j
    {
        const int h = warp;
        float v = s_qk[h][lane];
        float mx = v;
#pragma unroll
        for (int off = 16; off; off >>= 1)
            mx = fmaxf(mx, __shfl_xor_sync(0xFFFFFFFFu, mx, off));
        float e = expf(v - mx);
        float ssum = e;
#pragma unroll
        for (int off = 16; off; off >>= 1)
            ssum += __shfl_xor_sync(0xFFFFFFFFu, ssum, off);
        s_attn[h][lane] = e / ssum;

        float w = s_cw[lane][h];
        float mx2 = w;
#pragma unroll
        for (int off = 16; off; off >>= 1)
            mx2 = fmaxf(mx2, __shfl_xor_sync(0xFFFFFFFFu, mx2, off));
        float e2 = expf(w - mx2);
        float ssum2 = e2;
#pragma unroll
        for (int off = 16; off; off >>= 1)
            ssum2 += __shfl_xor_sync(0xFFFFFFFFu, ssum2, off);
        s_cw[lane][h] = e2 / ssum2;
    }
    __syncthreads();

    // coordinates output: warp 0, lane j = neighbor j
    if (warp == 0 && out_coors) {
        float w = 0.f;
#pragma unroll
        for (int h = 0; h < HEADS; h++)
            w += s_cw[lane][h] * s_gate[lane][h] * coors_combine[h];
        const int jj = s_idx[lane];
        const float nrm = fmaxf(s_dist[lane], 1e-8f);
        const float cscale = coors_scale[0] * w / nrm;
        float vx = (cix - cb[jj * 3 + 0]) * cscale;
        float vy = (ciy - cb[jj * 3 + 1]) * cscale;
        float vz = (ciz - cb[jj * 3 + 2]) * cscale;
#pragma unroll
        for (int off = 16; off; off >>= 1) {
            vx += __shfl_xor_sync(0xFFFFFFFFu, vx, off);
            vy += __shfl_xor_sync(0xFFFFFFFFu, vy, off);
            vz += __shfl_xor_sync(0xFFFFFFFFu, vz, off);
        }
        if (lane == 0) {
            out_coors[(long)row * 3 + 0] = vx;
            out_coors[(long)row * 3 + 1] = vy;
            out_coors[(long)row * 3 + 2] = vz;
        }
    }

    // feature output: lane l accumulates dims (2l, 2l+1).
    // vrot[2l]   = v[2l]  *C[l] + (l<16 ? -v[4l+1] : v[4l-64])*S[l]
    // vrot[2l+1] = v[2l+1]*C[l] + (l<16 ? -v[4l+3] : v[4l-62])*S[l]
    const int sA = (2 * lane) & 31;
    const int sB = (2 * lane + 1) & 31;
    const bool lo = lane < 16;
    float acc1 = 0.f, acc2 = 0.f;
#pragma unroll 4
    for (int r = 0; r < KNB; r++) {
        const long vb = (long)(b * NPTS + s_idx[r]) * QKVN + 2 * INNER + hb;
        float2 vv = *(const float2*)&g_qkv[vb + 2 * lane];
        float ya = __shfl_sync(0xFFFFFFFFu, vv.y, sA);
        float xa = __shfl_sync(0xFFFFFFFFu, vv.x, sA);
        float yb = __shfl_sync(0xFFFFFFFFu, vv.y, sB);
        float xb = __shfl_sync(0xFFFFFFFFu, vv.x, sB);
        float rot0 = lo ? -ya : xa;
        float rot1 = lo ? -yb : xb;
        float C = s_cos[r][lane];
        float S = s_sin[r][lane];
        float a = s_attn[warp][r];
        float t0 = fmaf(rot0, S, vv.x * C);
        float t1 = fmaf(rot1, S, vv.y * C);
        acc1 = fmaf(a, t0, acc1);
        acc2 = fmaf(a, t1, acc2);
    }
    *(float2*)&g_att[(long)row * INNER + hb + 2 * lane] = make_float2(acc1, acc2);
}

// ---------------------------------------------------------------------------
extern "C" void kernel_launch(void* const* d_in, const int* in_sizes, int n_in,
                              void* d_out, int out_size)
{
    const float* feats         = (const float*)d_in[0];
    const float* coors         = (const float*)d_in[1];
    const float* w_qkv         = (const float*)d_in[2];
    const float* w_out         = (const float*)d_in[3];
    const float* b_out         = (const float*)d_in[4];
    const float* wc1           = (const float*)d_in[5];
    const float* bc1           = (const float*)d_in[6];
    const float* wc2           = (const float*)d_in[7];
    const float* bc2           = (const float*)d_in[8];
    const float* wg            = (const float*)d_in[9];
    const float* bg            = (const float*)d_in[10];
    const float* coors_scale   = (const float*)d_in[11];
    const float* coors_combine = (const float*)d_in[12];

    float* out = (float*)d_out;
    float* out_coors = (out_size >= FEAT_OUT + ROWS * 3) ? out + FEAT_OUT : nullptr;

    float* qkv_ptr = nullptr;
    float* att_ptr = nullptr;
    cudaGetSymbolAddress((void**)&qkv_ptr, g_qkv);
    cudaGetSymbolAddress((void**)&att_ptr, g_att);

    cudaFuncSetAttribute(tf32_gemm_kernel,
                         cudaFuncAttributeMaxDynamicSharedMemorySize, GSMEM_BYTES);

    // 1) qkv = feats @ w_qkv  (TF32 tensor cores)
    {
        dim3 grid(QKVN / 128, ROWS / 128);
        tf32_gemm_kernel<<<grid, 256, GSMEM_BYTES>>>(feats, w_qkv, qkv_ptr,
                                                     ROWS, QKVN, DIMF, nullptr);
    }
    // 2) fused neighbor selection + attention
    sa_kernel<<<ROWS, 256>>>(coors, wc1, bc1, wc2, bc2, wg, bg,
                             coors_scale, coors_combine, out_coors);
    // 3) out = att @ w_out + b_out  (TF32 tensor cores)
    {
        dim3 grid(DIMF / 128, ROWS / 128);
        tf32_gemm_kernel<<<grid, 256, GSMEM_BYTES>>>(att_ptr, w_out, out,
                                                     ROWS, DIMF, INNER, b_out);
    }
}

// round 6
// speedup vs baseline: 1.1480x; 1.1480x over previous
#include <cuda_runtime.h>
#include <cuda_bf16.h>
#include <math.h>
#include <stdint.h>

// Problem constants
#define BATCH   2
#define NPTS    2048
#define HEADS   8
#define DHEAD   64
#define KNB     32
#define DIMF    512
#define INNER   512          // HEADS*DHEAD
#define QKVN    1536         // 3*INNER
#define ROWS    (BATCH*NPTS) // 4096
#define FEAT_OUT (ROWS*DIMF) // 2097152

#define INF_F __int_as_float(0x7F800000)

// Scratch (device globals: allocation-free per harness rules)
__device__ float g_qkv[ROWS * QKVN];   // 25.2 MB
__device__ float g_att[ROWS * INNER];  // 8.4 MB
__device__ int   g_nbr[ROWS * KNB];
__device__ float g_dst[ROWS * KNB];

// ---------------------------------------------------------------------------
// TF32 tensor-core GEMM with register-prefetch double buffering (R4 version).
// C[M,N] = A[M,K] @ B[K,N] (+ bias[N]); block 128x128x32, 8 warps (2x4),
// warp tile 64x32 via mma.sync.m16n8k8.
// ---------------------------------------------------------------------------
__device__ __forceinline__ uint32_t f2tf32(float x) {
    uint32_t r;
    asm("cvt.rna.tf32.f32 %0, %1;" : "=r"(r) : "f"(x));
    return r;
}

__global__ __launch_bounds__(256) void tf32_gemm_kernel(
    const float* __restrict__ A, const float* __restrict__ Bm,
    float* __restrict__ C, int M, int N, int K,
    const float* __restrict__ bias)
{
    constexpr int BM = 128, BN = 128, BK = 32;
    constexpr int AP = BK + 4;   // 36
    constexpr int BP = BN + 8;   // 136
    __shared__ uint32_t As[BM * AP];
    __shared__ uint32_t Bs[BK * BP];

    const int tid = threadIdx.x;
    const int lane = tid & 31;
    const int wid = tid >> 5;
    const int wm = wid & 1;
    const int wn = wid >> 1;
    const int row0 = blockIdx.y * BM;
    const int col0 = blockIdx.x * BN;

    const int g  = lane >> 2;
    const int tg = lane & 3;

    float acc[4][4][4];
#pragma unroll
    for (int i = 0; i < 4; i++)
#pragma unroll
        for (int j = 0; j < 4; j++)
#pragma unroll
            for (int r = 0; r < 4; r++) acc[i][j][r] = 0.f;

    const int ar = tid >> 3;           // 0..31 (+p*32)
    const int ac = (tid & 7) * 4;      // 0..28
    const int br = tid >> 5;           // 0..7  (+p*8)
    const int bc = (tid & 31) * 4;     // 0..124

    float4 pa[4], pb[4];
#pragma unroll
    for (int p = 0; p < 4; p++) {
        pa[p] = *(const float4*)&A[(long)(row0 + ar + p * 32) * K + ac];
        pb[p] = *(const float4*)&Bm[(long)(br + p * 8) * N + col0 + bc];
    }

    for (int kk = 0; kk < K; kk += BK) {
#pragma unroll
        for (int p = 0; p < 4; p++) {
            uint32_t* as = &As[(ar + p * 32) * AP + ac];
            as[0] = f2tf32(pa[p].x); as[1] = f2tf32(pa[p].y);
            as[2] = f2tf32(pa[p].z); as[3] = f2tf32(pa[p].w);
            uint32_t* bs = &Bs[(br + p * 8) * BP + bc];
            bs[0] = f2tf32(pb[p].x); bs[1] = f2tf32(pb[p].y);
            bs[2] = f2tf32(pb[p].z); bs[3] = f2tf32(pb[p].w);
        }
        __syncthreads();

        // prefetch next tile (overlaps with MMA below)
        if (kk + BK < K) {
#pragma unroll
            for (int p = 0; p < 4; p++) {
                pa[p] = *(const float4*)&A[(long)(row0 + ar + p * 32) * K + kk + BK + ac];
                pb[p] = *(const float4*)&Bm[(long)(kk + BK + br + p * 8) * N + col0 + bc];
            }
        }

#pragma unroll
        for (int ks = 0; ks < 4; ks++) {
            const int k0 = ks * 8;
            uint32_t a[4][4], b[4][2];
#pragma unroll
            for (int mi = 0; mi < 4; mi++) {
                const int r = wm * 64 + mi * 16 + g;
                a[mi][0] = As[r * AP + k0 + tg];
                a[mi][1] = As[(r + 8) * AP + k0 + tg];
                a[mi][2] = As[r * AP + k0 + tg + 4];
                a[mi][3] = As[(r + 8) * AP + k0 + tg + 4];
            }
#pragma unroll
            for (int nj = 0; nj < 4; nj++) {
                const int c = wn * 32 + nj * 8 + g;
                b[nj][0] = Bs[(k0 + tg) * BP + c];
                b[nj][1] = Bs[(k0 + tg + 4) * BP + c];
            }
#pragma unroll
            for (int mi = 0; mi < 4; mi++)
#pragma unroll
                for (int nj = 0; nj < 4; nj++) {
                    asm volatile(
                        "mma.sync.aligned.m16n8k8.row.col.f32.tf32.tf32.f32 "
                        "{%0,%1,%2,%3}, {%4,%5,%6,%7}, {%8,%9}, {%0,%1,%2,%3};"
                        : "+f"(acc[mi][nj][0]), "+f"(acc[mi][nj][1]),
                          "+f"(acc[mi][nj][2]), "+f"(acc[mi][nj][3])
                        : "r"(a[mi][0]), "r"(a[mi][1]), "r"(a[mi][2]), "r"(a[mi][3]),
                          "r"(b[nj][0]), "r"(b[nj][1]));
                }
        }
        __syncthreads();
    }

#pragma unroll
    for (int mi = 0; mi < 4; mi++) {
        const int r = row0 + wm * 64 + mi * 16 + g;
#pragma unroll
        for (int nj = 0; nj < 4; nj++) {
            const int c = col0 + wn * 32 + nj * 8 + 2 * tg;
            float b0 = bias ? bias[c] : 0.f;
            float b1 = bias ? bias[c + 1] : 0.f;
            C[(long)r * N + c]           = acc[mi][nj][0] + b0;
            C[(long)r * N + c + 1]       = acc[mi][nj][1] + b1;
            C[(long)(r + 8) * N + c]     = acc[mi][nj][2] + b0;
            C[(long)(r + 8) * N + c + 1] = acc[mi][nj][3] + b1;
        }
    }
}

// ---------------------------------------------------------------------------
// Selection kernel (R4 phase A/B, standalone for low reg pressure):
// per-warp top-32 (intra-warp, barrier-free) + single-warp merge.
// ---------------------------------------------------------------------------
__global__ __launch_bounds__(256) void select_kernel(
    const float* __restrict__ coors,
    int* __restrict__ nbr, float* __restrict__ dst)
{
    const int row = blockIdx.x;
    const int b = row >> 11;
    const int i = row & (NPTS - 1);
    const int tid = threadIdx.x;
    const int lane = tid & 31;
    const int warp = tid >> 5;

    __shared__ unsigned long long s_cand[256];
    __shared__ float s_ci[3];

    const float* cb = coors + (long)b * NPTS * 3;
    if (tid < 3) s_ci[tid] = cb[i * 3 + tid];
    __syncthreads();
    const float cix = s_ci[0], ciy = s_ci[1], ciz = s_ci[2];

    // squared distances: warp w owns points [w*256, w*256+256)
    float d2l[8];
#pragma unroll
    for (int u = 0; u < 8; u++) {
        int j = warp * 256 + u * 32 + lane;
        float dx = cix - cb[j * 3 + 0];
        float dy = ciy - cb[j * 3 + 1];
        float dz = ciz - cb[j * 3 + 2];
        d2l[u] = dx * dx + dy * dy + dz * dz;
    }

    // Phase A: per-warp top-32 (no barriers, no atomics)
    for (int r = 0; r < KNB; r++) {
        float mn = d2l[0]; int mu = 0;
#pragma unroll
        for (int u = 1; u < 8; u++)
            if (d2l[u] < mn) { mn = d2l[u]; mu = u; }
        unsigned long long key =
            ((unsigned long long)__float_as_uint(mn) << 32)
            | (unsigned)(warp * 256 + mu * 32 + lane);
#pragma unroll
        for (int off = 16; off; off >>= 1) {
            unsigned long long o = __shfl_xor_sync(0xFFFFFFFFu, key, off);
            key = min(key, o);
        }
        int wj = (int)(key & 0xFFFFFFFFu);
        if (lane == (wj & 31)) {
            int wu = (wj >> 5) & 7;
#pragma unroll
            for (int u = 0; u < 8; u++)
                if (u == wu) d2l[u] = INF_F;
        }
        if (lane == 0) s_cand[warp * KNB + r] = key;
    }
    __syncthreads();

    // Phase B: warp 0 merges 256 candidates -> global top-32
    if (warp == 0) {
        unsigned long long c[8];
#pragma unroll
        for (int u = 0; u < 8; u++) c[u] = s_cand[u * 32 + lane];
        for (int r = 0; r < KNB; r++) {
            unsigned long long key = c[0];
#pragma unroll
            for (int u = 1; u < 8; u++) key = min(key, c[u]);
#pragma unroll
            for (int off = 16; off; off >>= 1) {
                unsigned long long o = __shfl_xor_sync(0xFFFFFFFFu, key, off);
                key = min(key, o);
            }
#pragma unroll
            for (int u = 0; u < 8; u++)
                if (c[u] == key) c[u] = 0xFFFFFFFFFFFFFFFFULL;
            if (lane == 0) {
                nbr[(long)row * KNB + r] = (int)(key & 0xFFFFFFFFu);
                dst[(long)row * KNB + r] = sqrtf(__uint_as_float((unsigned)(key >> 32)));
            }
        }
    }
}

// ---------------------------------------------------------------------------
// Attention kernel (R4 internals, standalone). One block per query row.
// ---------------------------------------------------------------------------
__global__ __launch_bounds__(256) void attn_kernel(
    const float* __restrict__ coors,
    const int* __restrict__ nbr, const float* __restrict__ dst,
    const float* __restrict__ wc1, const float* __restrict__ bc1,
    const float* __restrict__ wc2, const float* __restrict__ bc2,
    const float* __restrict__ wg,  const float* __restrict__ bg,
    const float* __restrict__ coors_scale,
    const float* __restrict__ coors_combine,
    float* __restrict__ out_coors)
{
    const int row = blockIdx.x;
    const int b = row >> 11;
    const int i = row & (NPTS - 1);
    const int tid = threadIdx.x;
    const int lane = tid & 31;
    const int warp = tid >> 5;           // warp == head

    __shared__ int   s_idx[KNB];
    __shared__ float s_dist[KNB];
    __shared__ float s_cos[KNB][32];
    __shared__ float s_sin[KNB][32];
    __shared__ float s_qk[HEADS][KNB];
    __shared__ float s_attn[HEADS][KNB];
    __shared__ float s_cw[KNB][HEADS];
    __shared__ float s_gate[KNB][HEADS];
    __shared__ float s_hid[KNB][16];
    __shared__ float s_ci[3];

    if (tid < KNB) {
        s_idx[tid]  = nbr[(long)row * KNB + tid];
        s_dist[tid] = dst[(long)row * KNB + tid];
    }
    const float* cb = coors + (long)b * NPTS * 3;
    if (tid < 3) s_ci[tid] = cb[i * 3 + tid];
    __syncthreads();
    const float cix = s_ci[0], ciy = s_ci[1], ciz = s_ci[2];

    // rotary cos/sin: freqs[m] = min(dist*100,5000) * 10000^(-2m/64)
    for (int idx = tid; idx < KNB * 32; idx += 256) {
        int r = idx >> 5, m = idx & 31;
        float t = fminf(s_dist[r] * 100.0f, 5000.0f);
        float invf = exp2f((float)m * -0.41524099657040455f);
        float f = t * invf;
        float s, c;
        sincosf(f, &s, &c);
        s_cos[r][m] = c;
        s_sin[r][m] = s;
    }
    __syncthreads();

    const int hb = warp * DHEAD;
    const int fi1 = lane >> 1;
    const int fi2 = 16 + (lane >> 1);
    const int m1 = (2 * lane + 1) & 31;
    const int m2 = (2 * lane) & 31;
    const bool lo = lane < 16;

    const long qbase = (long)row * QKVN + hb;
    const float q1 = g_qkv[qbase + lane];
    const float q2 = g_qkv[qbase + lane + 32];

    // qk logits (barrier-free, per-warp)
#pragma unroll 4
    for (int r = 0; r < KNB; r++) {
        const long kb = (long)(b * NPTS + s_idx[r]) * QKVN + INNER + hb;
        float k1 = __ldg(&g_qkv[kb + lane]);
        float k2 = __ldg(&g_qkv[kb + lane + 32]);
        float sa = __shfl_sync(0xFFFFFFFFu, k1, m1);
        float sb = __shfl_sync(0xFFFFFFFFu, k2, m1);
        float sc = __shfl_sync(0xFFFFFFFFu, k1, m2);
        float sd = __shfl_sync(0xFFFFFFFFu, k2, m2);
        float rh1 = -(lo ? sa : sb);
        float rh2 =  (lo ? sc : sd);
        float c1 = s_cos[r][fi1], sn1 = s_sin[r][fi1];
        float c2 = s_cos[r][fi2], sn2 = s_sin[r][fi2];
        float sum = q1 * (k1 * c1 + rh1 * sn1)
                  + q2 * (k2 * c2 + rh2 * sn2);
#pragma unroll
        for (int off = 16; off; off >>= 1)
            sum += __shfl_down_sync(0xFFFFFFFFu, sum, off);
        if (lane == 0) s_qk[warp][r] = sum * 0.125f;
    }
    __syncthreads();

    // tiny MLPs, parallel over (neighbor j, head/slot s): tid = j*8 + s
    {
        const int j = tid >> 3;
        const int s = tid & 7;
        float in[HEADS];
#pragma unroll
        for (int h = 0; h < HEADS; h++) in[h] = s_qk[h][j];
#pragma unroll
        for (int t = 0; t < 2; t++) {
            const int m = 2 * s + t;
            float a = bc1[m];
#pragma unroll
            for (int h = 0; h < HEADS; h++) a += in[h] * wc1[h * 16 + m];
            float x3 = a * a * a;
            float tt = tanhf(0.7978845608028654f * (a + 0.044715f * x3));
            s_hid[j][m] = 0.5f * a * (1.0f + tt);
        }
        __syncwarp();
        float a = bc2[s];
#pragma unroll
        for (int m = 0; m < 16; m++) a += s_hid[j][m] * wc2[m * 8 + s];
        s_cw[j][s] = a;
        float gg = bg[s];
#pragma unroll
        for (int h = 0; h < HEADS; h++) gg += in[h] * wg[h * 8 + s];
        s_gate[j][s] = tanhf(gg);
    }
    __syncthreads();

    // softmaxes: warp h handles head h, lane j handles neighbor j
    {
        const int h = warp;
        float v = s_qk[h][lane];
        float mx = v;
#pragma unroll
        for (int off = 16; off; off >>= 1)
            mx = fmaxf(mx, __shfl_xor_sync(0xFFFFFFFFu, mx, off));
        float e = expf(v - mx);
        float ssum = e;
#pragma unroll
        for (int off = 16; off; off >>= 1)
            ssum += __shfl_xor_sync(0xFFFFFFFFu, ssum, off);
        s_attn[h][lane] = e / ssum;

        float w = s_cw[lane][h];
        float mx2 = w;
#pragma unroll
        for (int off = 16; off; off >>= 1)
            mx2 = fmaxf(mx2, __shfl_xor_sync(0xFFFFFFFFu, mx2, off));
        float e2 = expf(w - mx2);
        float ssum2 = e2;
#pragma unroll
        for (int off = 16; off; off >>= 1)
            ssum2 += __shfl_xor_sync(0xFFFFFFFFu, ssum2, off);
        s_cw[lane][h] = e2 / ssum2;
    }
    __syncthreads();

    // coordinates output: warp 0, lane j = neighbor j
    if (warp == 0 && out_coors) {
        float w = 0.f;
#pragma unroll
        for (int h = 0; h < HEADS; h++)
            w += s_cw[lane][h] * s_gate[lane][h] * coors_combine[h];
        const int jj = s_idx[lane];
        const float nrm = fmaxf(s_dist[lane], 1e-8f);
        const float cscale = coors_scale[0] * w / nrm;
        float vx = (cix - cb[jj * 3 + 0]) * cscale;
        float vy = (ciy - cb[jj * 3 + 1]) * cscale;
        float vz = (ciz - cb[jj * 3 + 2]) * cscale;
#pragma unroll
        for (int off = 16; off; off >>= 1) {
            vx += __shfl_xor_sync(0xFFFFFFFFu, vx, off);
            vy += __shfl_xor_sync(0xFFFFFFFFu, vy, off);
            vz += __shfl_xor_sync(0xFFFFFFFFu, vz, off);
        }
        if (lane == 0) {
            out_coors[(long)row * 3 + 0] = vx;
            out_coors[(long)row * 3 + 1] = vy;
            out_coors[(long)row * 3 + 2] = vz;
        }
    }

    // feature output (barrier-free, per-warp)
    float acc1 = 0.f, acc2 = 0.f;
#pragma unroll 4
    for (int r = 0; r < KNB; r++) {
        const long vb = (long)(b * NPTS + s_idx[r]) * QKVN + 2 * INNER + hb;
        float v1 = __ldg(&g_qkv[vb + lane]);
        float v2 = __ldg(&g_qkv[vb + lane + 32]);
        float sa = __shfl_sync(0xFFFFFFFFu, v1, m1);
        float sb = __shfl_sync(0xFFFFFFFFu, v2, m1);
        float sc = __shfl_sync(0xFFFFFFFFu, v1, m2);
        float sd = __shfl_sync(0xFFFFFFFFu, v2, m2);
        float rh1 = -(lo ? sa : sb);
        float rh2 =  (lo ? sc : sd);
        float c1 = s_cos[r][fi1], sn1 = s_sin[r][fi1];
        float c2 = s_cos[r][fi2], sn2 = s_sin[r][fi2];
        float a = s_attn[warp][r];
        acc1 += a * (v1 * c1 + rh1 * sn1);
        acc2 += a * (v2 * c2 + rh2 * sn2);
    }
    g_att[(long)row * INNER + hb + lane] = acc1;
    g_att[(long)row * INNER + hb + lane + 32] = acc2;
}

// ---------------------------------------------------------------------------
extern "C" void kernel_launch(void* const* d_in, const int* in_sizes, int n_in,
                              void* d_out, int out_size)
{
    const float* feats         = (const float*)d_in[0];
    const float* coors         = (const float*)d_in[1];
    const float* w_qkv         = (const float*)d_in[2];
    const float* w_out         = (const float*)d_in[3];
    const float* b_out         = (const float*)d_in[4];
    const float* wc1           = (const float*)d_in[5];
    const float* bc1           = (const float*)d_in[6];
    const float* wc2           = (const float*)d_in[7];
    const float* bc2           = (const float*)d_in[8];
    const float* wg            = (const float*)d_in[9];
    const float* bg            = (const float*)d_in[10];
    const float* coors_scale   = (const float*)d_in[11];
    const float* coors_combine = (const float*)d_in[12];

    float* out = (float*)d_out;
    float* out_coors = (out_size >= FEAT_OUT + ROWS * 3) ? out + FEAT_OUT : nullptr;

    float* qkv_ptr = nullptr;
    float* att_ptr = nullptr;
    int*   nbr_ptr = nullptr;
    float* dst_ptr = nullptr;
    cudaGetSymbolAddress((void**)&qkv_ptr, g_qkv);
    cudaGetSymbolAddress((void**)&att_ptr, g_att);
    cudaGetSymbolAddress((void**)&nbr_ptr, g_nbr);
    cudaGetSymbolAddress((void**)&dst_ptr, g_dst);

    // 1) qkv = feats @ w_qkv  (TF32 tensor cores)
    {
        dim3 grid(QKVN / 128, ROWS / 128);
        tf32_gemm_kernel<<<grid, 256>>>(feats, w_qkv, qkv_ptr, ROWS, QKVN, DIMF, nullptr);
    }
    // 2a) neighbor selection
    select_kernel<<<ROWS, 256>>>(coors, nbr_ptr, dst_ptr);
    // 2b) per-row neighbor attention
    attn_kernel<<<ROWS, 256>>>(coors, nbr_ptr, dst_ptr,
                               wc1, bc1, wc2, bc2, wg, bg,
                               coors_scale, coors_combine, out_coors);
    // 3) out = att @ w_out + b_out  (TF32 tensor cores)
    {
        dim3 grid(DIMF / 128, ROWS / 128);
        tf32_gemm_kernel<<<grid, 256>>>(att_ptr, w_out, out, ROWS, DIMF, INNER, b_out);
    }
}

// round 7
// speedup vs baseline: 1.2690x; 1.1054x over previous
#include <cuda_runtime.h>
#include <cuda_bf16.h>
#include <math.h>
#include <stdint.h>

// Problem constants
#define BATCH   2
#define NPTS    2048
#define HEADS   8
#define DHEAD   64
#define KNB     32
#define DIMF    512
#define INNER   512          // HEADS*DHEAD
#define QKVN    1536         // 3*INNER
#define ROWS    (BATCH*NPTS) // 4096
#define FEAT_OUT (ROWS*DIMF) // 2097152

#define INF_F __int_as_float(0x7F800000)

// Scratch (device globals: allocation-free per harness rules)
__device__ float g_qkv[ROWS * QKVN];   // 25.2 MB
__device__ float g_att[ROWS * INNER];  // 8.4 MB

// ---------------------------------------------------------------------------
// TF32 tensor-core GEMM with register-prefetch double buffering (R4 version).
// C[M,N] = A[M,K] @ B[K,N] (+ bias[N]); block 128x128x32, 8 warps (2x4),
// warp tile 64x32 via mma.sync.m16n8k8.
// ---------------------------------------------------------------------------
__device__ __forceinline__ uint32_t f2tf32(float x) {
    uint32_t r;
    asm("cvt.rna.tf32.f32 %0, %1;" : "=r"(r) : "f"(x));
    return r;
}

__global__ __launch_bounds__(256) void tf32_gemm_kernel(
    const float* __restrict__ A, const float* __restrict__ Bm,
    float* __restrict__ C, int M, int N, int K,
    const float* __restrict__ bias)
{
    constexpr int BM = 128, BN = 128, BK = 32;
    constexpr int AP = BK + 4;   // 36
    constexpr int BP = BN + 8;   // 136
    __shared__ uint32_t As[BM * AP];
    __shared__ uint32_t Bs[BK * BP];

    const int tid = threadIdx.x;
    const int lane = tid & 31;
    const int wid = tid >> 5;
    const int wm = wid & 1;
    const int wn = wid >> 1;
    const int row0 = blockIdx.y * BM;
    const int col0 = blockIdx.x * BN;

    const int g  = lane >> 2;
    const int tg = lane & 3;

    float acc[4][4][4];
#pragma unroll
    for (int i = 0; i < 4; i++)
#pragma unroll
        for (int j = 0; j < 4; j++)
#pragma unroll
            for (int r = 0; r < 4; r++) acc[i][j][r] = 0.f;

    const int ar = tid >> 3;           // 0..31 (+p*32)
    const int ac = (tid & 7) * 4;      // 0..28
    const int br = tid >> 5;           // 0..7  (+p*8)
    const int bc = (tid & 31) * 4;     // 0..124

    float4 pa[4], pb[4];
#pragma unroll
    for (int p = 0; p < 4; p++) {
        pa[p] = *(const float4*)&A[(long)(row0 + ar + p * 32) * K + ac];
        pb[p] = *(const float4*)&Bm[(long)(br + p * 8) * N + col0 + bc];
    }

    for (int kk = 0; kk < K; kk += BK) {
#pragma unroll
        for (int p = 0; p < 4; p++) {
            uint32_t* as = &As[(ar + p * 32) * AP + ac];
            as[0] = f2tf32(pa[p].x); as[1] = f2tf32(pa[p].y);
            as[2] = f2tf32(pa[p].z); as[3] = f2tf32(pa[p].w);
            uint32_t* bs = &Bs[(br + p * 8) * BP + bc];
            bs[0] = f2tf32(pb[p].x); bs[1] = f2tf32(pb[p].y);
            bs[2] = f2tf32(pb[p].z); bs[3] = f2tf32(pb[p].w);
        }
        __syncthreads();

        // prefetch next tile (overlaps with MMA below)
        if (kk + BK < K) {
#pragma unroll
            for (int p = 0; p < 4; p++) {
                pa[p] = *(const float4*)&A[(long)(row0 + ar + p * 32) * K + kk + BK + ac];
                pb[p] = *(const float4*)&Bm[(long)(kk + BK + br + p * 8) * N + col0 + bc];
            }
        }

#pragma unroll
        for (int ks = 0; ks < 4; ks++) {
            const int k0 = ks * 8;
            uint32_t a[4][4], b[4][2];
#pragma unroll
            for (int mi = 0; mi < 4; mi++) {
                const int r = wm * 64 + mi * 16 + g;
                a[mi][0] = As[r * AP + k0 + tg];
                a[mi][1] = As[(r + 8) * AP + k0 + tg];
                a[mi][2] = As[r * AP + k0 + tg + 4];
                a[mi][3] = As[(r + 8) * AP + k0 + tg + 4];
            }
#pragma unroll
            for (int nj = 0; nj < 4; nj++) {
                const int c = wn * 32 + nj * 8 + g;
                b[nj][0] = Bs[(k0 + tg) * BP + c];
                b[nj][1] = Bs[(k0 + tg + 4) * BP + c];
            }
#pragma unroll
            for (int mi = 0; mi < 4; mi++)
#pragma unroll
                for (int nj = 0; nj < 4; nj++) {
                    asm volatile(
                        "mma.sync.aligned.m16n8k8.row.col.f32.tf32.tf32.f32 "
                        "{%0,%1,%2,%3}, {%4,%5,%6,%7}, {%8,%9}, {%0,%1,%2,%3};"
                        : "+f"(acc[mi][nj][0]), "+f"(acc[mi][nj][1]),
                          "+f"(acc[mi][nj][2]), "+f"(acc[mi][nj][3])
                        : "r"(a[mi][0]), "r"(a[mi][1]), "r"(a[mi][2]), "r"(a[mi][3]),
                          "r"(b[nj][0]), "r"(b[nj][1]));
                }
        }
        __syncthreads();
    }

#pragma unroll
    for (int mi = 0; mi < 4; mi++) {
        const int r = row0 + wm * 64 + mi * 16 + g;
#pragma unroll
        for (int nj = 0; nj < 4; nj++) {
            const int c = col0 + wn * 32 + nj * 8 + 2 * tg;
            float b0 = bias ? bias[c] : 0.f;
            float b1 = bias ? bias[c + 1] : 0.f;
            C[(long)r * N + c]           = acc[mi][nj][0] + b0;
            C[(long)r * N + c + 1]       = acc[mi][nj][1] + b1;
            C[(long)(r + 8) * N + c]     = acc[mi][nj][2] + b0;
            C[(long)(r + 8) * N + c + 1] = acc[mi][nj][3] + b1;
        }
    }
}

// ---------------------------------------------------------------------------
// Fused selection + attention kernel (R4 structure + fast sincos).
// One block (256 threads) per query row.
// ---------------------------------------------------------------------------
__global__ __launch_bounds__(256) void sa_kernel(
    const float* __restrict__ coors,
    const float* __restrict__ wc1, const float* __restrict__ bc1,
    const float* __restrict__ wc2, const float* __restrict__ bc2,
    const float* __restrict__ wg,  const float* __restrict__ bg,
    const float* __restrict__ coors_scale,
    const float* __restrict__ coors_combine,
    float* __restrict__ out_coors)
{
    const int row = blockIdx.x;
    const int b = row >> 11;             // / NPTS
    const int i = row & (NPTS - 1);
    const int tid = threadIdx.x;
    const int lane = tid & 31;
    const int warp = tid >> 5;           // warp == head

    __shared__ unsigned long long s_cand[256];
    __shared__ int   s_idx[KNB];
    __shared__ float s_dist[KNB];
    __shared__ float s_cos[KNB][32];
    __shared__ float s_sin[KNB][32];
    __shared__ float s_qk[HEADS][KNB];
    __shared__ float s_attn[HEADS][KNB];
    __shared__ float s_cw[KNB][HEADS];
    __shared__ float s_gate[KNB][HEADS];
    __shared__ float s_hid[KNB][16];
    __shared__ float s_ci[3];

    const float* cb = coors + (long)b * NPTS * 3;
    if (tid < 3) s_ci[tid] = cb[i * 3 + tid];
    __syncthreads();
    const float cix = s_ci[0], ciy = s_ci[1], ciz = s_ci[2];

    // q prefetch (rotary with zero freqs is identity)
    const int hb = warp * DHEAD;
    const long qbase = (long)row * QKVN + hb;
    const float q1 = g_qkv[qbase + lane];
    const float q2 = g_qkv[qbase + lane + 32];

    // squared distances: warp w owns points [w*256, w*256+256)
    float d2l[8];
#pragma unroll
    for (int u = 0; u < 8; u++) {
        int j = warp * 256 + u * 32 + lane;
        float dx = cix - cb[j * 3 + 0];
        float dy = ciy - cb[j * 3 + 1];
        float dz = ciz - cb[j * 3 + 2];
        d2l[u] = dx * dx + dy * dy + dz * dz;
    }

    // Phase A: per-warp top-32 (no barriers, no atomics)
    for (int r = 0; r < KNB; r++) {
        float mn = d2l[0]; int mu = 0;
#pragma unroll
        for (int u = 1; u < 8; u++)
            if (d2l[u] < mn) { mn = d2l[u]; mu = u; }
        unsigned long long key =
            ((unsigned long long)__float_as_uint(mn) << 32)
            | (unsigned)(warp * 256 + mu * 32 + lane);
#pragma unroll
        for (int off = 16; off; off >>= 1) {
            unsigned long long o = __shfl_xor_sync(0xFFFFFFFFu, key, off);
            key = min(key, o);
        }
        int wj = (int)(key & 0xFFFFFFFFu);
        if (lane == (wj & 31)) {
            int wu = (wj >> 5) & 7;
#pragma unroll
            for (int u = 0; u < 8; u++)
                if (u == wu) d2l[u] = INF_F;
        }
        if (lane == 0) s_cand[warp * KNB + r] = key;
    }
    __syncthreads();

    // Phase B: warp 0 merges 256 candidates -> global top-32
    if (warp == 0) {
        unsigned long long c[8];
#pragma unroll
        for (int u = 0; u < 8; u++) c[u] = s_cand[u * 32 + lane];
        for (int r = 0; r < KNB; r++) {
            unsigned long long key = c[0];
#pragma unroll
            for (int u = 1; u < 8; u++) key = min(key, c[u]);
#pragma unroll
            for (int off = 16; off; off >>= 1) {
                unsigned long long o = __shfl_xor_sync(0xFFFFFFFFu, key, off);
                key = min(key, o);
            }
#pragma unroll
            for (int u = 0; u < 8; u++)
                if (c[u] == key) c[u] = 0xFFFFFFFFFFFFFFFFULL;
            if (lane == 0) {
                s_idx[r]  = (int)(key & 0xFFFFFFFFu);
                s_dist[r] = sqrtf(__uint_as_float((unsigned)(key >> 32)));
            }
        }
    }
    __syncthreads();

    // rotary cos/sin: freqs[m] = min(dist*100,5000) * 10000^(-2m/64)
    // m = tid & 31 is loop-invariant -> hoist exp2f; use HW sincos (RRO+MUFU).
    {
        const int m = tid & 31;
        const float invf = exp2f((float)m * -0.41524099657040455f);
#pragma unroll
        for (int idx = tid; idx < KNB * 32; idx += 256) {
            int r = idx >> 5;
            float t = fminf(s_dist[r] * 100.0f, 5000.0f);
            float s, c;
            __sincosf(t * invf, &s, &c);
            s_cos[r][m] = c;
            s_sin[r][m] = s;
        }
    }
    __syncthreads();

    const int fi1 = lane >> 1;
    const int fi2 = 16 + (lane >> 1);
    const int m1 = (2 * lane + 1) & 31;
    const int m2 = (2 * lane) & 31;
    const bool lo = lane < 16;

    // qk logits (barrier-free, per-warp)
#pragma unroll 4
    for (int r = 0; r < KNB; r++) {
        const long kb = (long)(b * NPTS + s_idx[r]) * QKVN + INNER + hb;
        float k1 = __ldg(&g_qkv[kb + lane]);
        float k2 = __ldg(&g_qkv[kb + lane + 32]);
        float sa = __shfl_sync(0xFFFFFFFFu, k1, m1);
        float sb = __shfl_sync(0xFFFFFFFFu, k2, m1);
        float sc = __shfl_sync(0xFFFFFFFFu, k1, m2);
        float sd = __shfl_sync(0xFFFFFFFFu, k2, m2);
        float rh1 = -(lo ? sa : sb);
        float rh2 =  (lo ? sc : sd);
        float c1 = s_cos[r][fi1], sn1 = s_sin[r][fi1];
        float c2 = s_cos[r][fi2], sn2 = s_sin[r][fi2];
        float sum = q1 * (k1 * c1 + rh1 * sn1)
                  + q2 * (k2 * c2 + rh2 * sn2);
#pragma unroll
        for (int off = 16; off; off >>= 1)
            sum += __shfl_down_sync(0xFFFFFFFFu, sum, off);
        if (lane == 0) s_qk[warp][r] = sum * 0.125f;
    }
    __syncthreads();

    // tiny MLPs, parallel over (neighbor j, head/slot s): tid = j*8 + s
    {
        const int j = tid >> 3;
        const int s = tid & 7;
        float in[HEADS];
#pragma unroll
        for (int h = 0; h < HEADS; h++) in[h] = s_qk[h][j];
#pragma unroll
        for (int t = 0; t < 2; t++) {
            const int m = 2 * s + t;
            float a = bc1[m];
#pragma unroll
            for (int h = 0; h < HEADS; h++) a += in[h] * wc1[h * 16 + m];
            float x3 = a * a * a;
            float tt = tanhf(0.7978845608028654f * (a + 0.044715f * x3));
            s_hid[j][m] = 0.5f * a * (1.0f + tt);
        }
        __syncwarp();
        float a = bc2[s];
#pragma unroll
        for (int m = 0; m < 16; m++) a += s_hid[j][m] * wc2[m * 8 + s];
        s_cw[j][s] = a;
        float gg = bg[s];
#pragma unroll
        for (int h = 0; h < HEADS; h++) gg += in[h] * wg[h * 8 + s];
        s_gate[j][s] = tanhf(gg);
    }
    __syncthreads();

    // softmaxes: warp h handles head h, lane j handles neighbor j
    {
        const int h = warp;
        float v = s_qk[h][lane];
        float mx = v;
#pragma unroll
        for (int off = 16; off; off >>= 1)
            mx = fmaxf(mx, __shfl_xor_sync(0xFFFFFFFFu, mx, off));
        float e = expf(v - mx);
        float ssum = e;
#pragma unroll
        for (int off = 16; off; off >>= 1)
            ssum += __shfl_xor_sync(0xFFFFFFFFu, ssum, off);
        s_attn[h][lane] = e / ssum;

        float w = s_cw[lane][h];
        float mx2 = w;
#pragma unroll
        for (int off = 16; off; off >>= 1)
            mx2 = fmaxf(mx2, __shfl_xor_sync(0xFFFFFFFFu, mx2, off));
        float e2 = expf(w - mx2);
        float ssum2 = e2;
#pragma unroll
        for (int off = 16; off; off >>= 1)
            ssum2 += __shfl_xor_sync(0xFFFFFFFFu, ssum2, off);
        s_cw[lane][h] = e2 / ssum2;
    }
    __syncthreads();

    // coordinates output: warp 0, lane j = neighbor j
    if (warp == 0 && out_coors) {
        float w = 0.f;
#pragma unroll
        for (int h = 0; h < HEADS; h++)
            w += s_cw[lane][h] * s_gate[lane][h] * coors_combine[h];
        const int jj = s_idx[lane];
        const float nrm = fmaxf(s_dist[lane], 1e-8f);
        const float cscale = coors_scale[0] * w / nrm;
        float vx = (cix - cb[jj * 3 + 0]) * cscale;
        float vy = (ciy - cb[jj * 3 + 1]) * cscale;
        float vz = (ciz - cb[jj * 3 + 2]) * cscale;
#pragma unroll
        for (int off = 16; off; off >>= 1) {
            vx += __shfl_xor_sync(0xFFFFFFFFu, vx, off);
            vy += __shfl_xor_sync(0xFFFFFFFFu, vy, off);
            vz += __shfl_xor_sync(0xFFFFFFFFu, vz, off);
        }
        if (lane == 0) {
            out_coors[(long)row * 3 + 0] = vx;
            out_coors[(long)row * 3 + 1] = vy;
            out_coors[(long)row * 3 + 2] = vz;
        }
    }

    // feature output (barrier-free, per-warp)
    float acc1 = 0.f, acc2 = 0.f;
#pragma unroll 4
    for (int r = 0; r < KNB; r++) {
        const long vb = (long)(b * NPTS + s_idx[r]) * QKVN + 2 * INNER + hb;
        float v1 = __ldg(&g_qkv[vb + lane]);
        float v2 = __ldg(&g_qkv[vb + lane + 32]);
        float sa = __shfl_sync(0xFFFFFFFFu, v1, m1);
        float sb = __shfl_sync(0xFFFFFFFFu, v2, m1);
        float sc = __shfl_sync(0xFFFFFFFFu, v1, m2);
        float sd = __shfl_sync(0xFFFFFFFFu, v2, m2);
        float rh1 = -(lo ? sa : sb);
        float rh2 =  (lo ? sc : sd);
        float c1 = s_cos[r][fi1], sn1 = s_sin[r][fi1];
        float c2 = s_cos[r][fi2], sn2 = s_sin[r][fi2];
        float a = s_attn[warp][r];
        acc1 += a * (v1 * c1 + rh1 * sn1);
        acc2 += a * (v2 * c2 + rh2 * sn2);
    }
    g_att[(long)row * INNER + hb + lane] = acc1;
    g_att[(long)row * INNER + hb + lane + 32] = acc2;
}

// ---------------------------------------------------------------------------
extern "C" void kernel_launch(void* const* d_in, const int* in_sizes, int n_in,
                              void* d_out, int out_size)
{
    const float* feats         = (const float*)d_in[0];
    const float* coors         = (const float*)d_in[1];
    const float* w_qkv         = (const float*)d_in[2];
    const float* w_out         = (const float*)d_in[3];
    const float* b_out         = (const float*)d_in[4];
    const float* wc1           = (const float*)d_in[5];
    const float* bc1           = (const float*)d_in[6];
    const float* wc2           = (const float*)d_in[7];
    const float* bc2           = (const float*)d_in[8];
    const float* wg            = (const float*)d_in[9];
    const float* bg            = (const float*)d_in[10];
    const float* coors_scale   = (const float*)d_in[11];
    const float* coors_combine = (const float*)d_in[12];

    float* out = (float*)d_out;
    float* out_coors = (out_size >= FEAT_OUT + ROWS * 3) ? out + FEAT_OUT : nullptr;

    float* qkv_ptr = nullptr;
    float* att_ptr = nullptr;
    cudaGetSymbolAddress((void**)&qkv_ptr, g_qkv);
    cudaGetSymbolAddress((void**)&att_ptr, g_att);

    // 1) qkv = feats @ w_qkv  (TF32 tensor cores)
    {
        dim3 grid(QKVN / 128, ROWS / 128);
        tf32_gemm_kernel<<<grid, 256>>>(feats, w_qkv, qkv_ptr, ROWS, QKVN, DIMF, nullptr);
    }
    // 2) fused neighbor selection + attention
    sa_kernel<<<ROWS, 256>>>(coors, wc1, bc1, wc2, bc2, wg, bg,
                             coors_scale, coors_combine, out_coors);
    // 3) out = att @ w_out + b_out  (TF32 tensor cores)
    {
        dim3 grid(DIMF / 128, ROWS / 128);
        tf32_gemm_kernel<<<grid, 256>>>(att_ptr, w_out, out, ROWS, DIMF, INNER, b_out);
    }
}